// round 9
// baseline (speedup 1.0000x reference)
#include <cuda_runtime.h>

// Problem constants (fixed by setup_inputs)
#define Bn   16
#define D    1024
#define H    16
#define HD   64
#define S    4096
#define SP   4097          // S + 1
#define SPAD 4112          // padded score row stride

// key pass (register-direct): 8 lanes per row, 2 rows per thread
#define KRPB 64            // rows per block (256 thr / 8 lanes * 2 rows)
#define KNC  65            // ceil(4097/64)
#define KPF  4             // rolling prefetch depth per row
#define KSMEM_BYTES (H * D * 4)   // 64 KB qw tile

// value pass (register-direct, unchanged from R5)
#define VCH  128
#define VNC  33
#define PF   8

// Scratch (device globals; no allocation allowed)
__device__ float g_qw[Bn * H * D];
__device__ float g_scores[Bn * H * SPAD];
__device__ float g_avpart[(size_t)Bn * VNC * H * D];
__device__ float g_ctx[Bn * D];

// ---------------------------------------------------------------------------
// Kernel 1: q projection folded through wk. grid (H, B), 256 threads.
// ---------------------------------------------------------------------------
__global__ void __launch_bounds__(256) k_qproj(const float* __restrict__ query,
                                               const float* __restrict__ w_in,
                                               const float* __restrict__ b_in) {
    __shared__ float qs[D];
    __shared__ float qh[HD];
    const int h = blockIdx.x, b = blockIdx.y, tid = threadIdx.x;

    for (int i = tid; i < D; i += 256) qs[i] = query[b * D + i];
    __syncthreads();

    {
        int d = tid >> 2, sub = tid & 3;
        const float* wrow = w_in + (size_t)(h * HD + d) * D;
        float a = 0.f;
        #pragma unroll 8
        for (int e = sub; e < D; e += 4) a = fmaf(qs[e], wrow[e], a);
        a += __shfl_down_sync(0xffffffffu, a, 2, 4);
        a += __shfl_down_sync(0xffffffffu, a, 1, 4);
        if (sub == 0) qh[d] = (a + b_in[h * HD + d]) * 0.125f;
    }
    __syncthreads();

    for (int e = tid; e < D; e += 256) {
        float a = 0.f;
        #pragma unroll
        for (int d = 0; d < HD; d++)
            a = fmaf(qh[d], w_in[(size_t)(D + h * HD + d) * D + e], a);
        g_qw[(b * H + h) * D + e] = a;
    }
}

// ---------------------------------------------------------------------------
// Kernel 2: key pass — register-direct.
//   8 lanes per key row (lane e-offset (tid&7)*4, stride 32 floats).
//   Thread owns rows r and r+32; per float4 step: 2 LDG + 2 STG(comb_key)
//   + 16 broadcast LDS(qw) + 128 FMA into 32 scalar accumulators.
//   qw tile (64 KB) staged once; no barriers in the e loop.
// grid (KNC, B), 256 threads.
// ---------------------------------------------------------------------------
__global__ void __launch_bounds__(256, 2) k_keys(const float* __restrict__ past_key,
                                                 const float* __restrict__ key,
                                                 float* __restrict__ comb_key) {
    extern __shared__ float qws[];         // [H][D]
    const int chunk = blockIdx.x, b = blockIdx.y, tid = threadIdx.x;
    const int k0 = chunk * KRPB;
    const int rid = tid >> 3;              // 0..31
    const int foff = (tid & 7) * 4;        // float offset within 32-float group

    // stage qw[b] into smem (contiguous 64 KB)
    {
        const float4* src = (const float4*)(g_qw + (size_t)b * H * D);
        float4* dst = (float4*)qws;
        for (int i = tid; i < H * D / 4; i += 256) dst[i] = src[i];
    }
    __syncthreads();

    const int kr0 = k0 + rid, kr1 = k0 + rid + 32;
    const float* src0 = ((kr0 < S) ? past_key + ((size_t)b * S + kr0) * D
                                   : key + (size_t)b * D) + foff;
    const float* src1 = ((kr1 < S) ? past_key + ((size_t)b * S + kr1) * D
                                   : key + (size_t)b * D) + foff;
    float* dst0 = comb_key + ((size_t)b * SP + kr0) * D + foff;
    float* dst1 = comb_key + ((size_t)b * SP + kr1) * D + foff;
    const bool ok0 = kr0 < SP, ok1 = kr1 < SP;

    float acc0[16], acc1[16];
    #pragma unroll
    for (int h = 0; h < 16; h++) { acc0[h] = 0.f; acc1[h] = 0.f; }

    float4 vb0[KPF], vb1[KPF];
    #pragma unroll
    for (int p = 0; p < KPF; p++) {
        vb0[p] = *(const float4*)(src0 + 32 * p);
        vb1[p] = *(const float4*)(src1 + 32 * p);
    }

    for (int jb = 0; jb < 32; jb += KPF) {
        #pragma unroll
        for (int p = 0; p < KPF; p++) {
            const int j = jb + p;
            const float4 v0 = vb0[p];
            const float4 v1 = vb1[p];

            if (jb + KPF < 32) {
                vb0[p] = *(const float4*)(src0 + 32 * (j + KPF));
                vb1[p] = *(const float4*)(src1 + 32 * (j + KPF));
            }
            if (ok0) *(float4*)(dst0 + 32 * j) = v0;
            if (ok1) *(float4*)(dst1 + 32 * j) = v1;

            const float* qbase = qws + foff + 32 * j;
            #pragma unroll
            for (int h = 0; h < 16; h++) {
                float4 w = *(const float4*)(qbase + h * D);
                acc0[h] = fmaf(v0.x, w.x, acc0[h]);
                acc0[h] = fmaf(v0.y, w.y, acc0[h]);
                acc0[h] = fmaf(v0.z, w.z, acc0[h]);
                acc0[h] = fmaf(v0.w, w.w, acc0[h]);
                acc1[h] = fmaf(v1.x, w.x, acc1[h]);
                acc1[h] = fmaf(v1.y, w.y, acc1[h]);
                acc1[h] = fmaf(v1.z, w.z, acc1[h]);
                acc1[h] = fmaf(v1.w, w.w, acc1[h]);
            }
        }
    }

    // reduce over the 8 lanes of each row group, lane 0 stores
    #pragma unroll
    for (int h = 0; h < 16; h++) {
        float a0 = acc0[h], a1 = acc1[h];
        a0 += __shfl_down_sync(0xffffffffu, a0, 4, 8);
        a0 += __shfl_down_sync(0xffffffffu, a0, 2, 8);
        a0 += __shfl_down_sync(0xffffffffu, a0, 1, 8);
        a1 += __shfl_down_sync(0xffffffffu, a1, 4, 8);
        a1 += __shfl_down_sync(0xffffffffu, a1, 2, 8);
        a1 += __shfl_down_sync(0xffffffffu, a1, 1, 8);
        if ((tid & 7) == 0) {
            if (ok0) g_scores[(size_t)(b * H + h) * SPAD + kr0] = a0;
            if (ok1) g_scores[(size_t)(b * H + h) * SPAD + kr1] = a1;
        }
    }
}

// ---------------------------------------------------------------------------
// Kernel 3: softmax over 4097 scores per (b,h); in place. grid 256, 256 thr.
// ---------------------------------------------------------------------------
__global__ void k_softmax() {
    __shared__ float red[32];
    __shared__ float bc;
    const int tid = threadIdx.x, lane = tid & 31, wid = tid >> 5;
    float* row = g_scores + (size_t)blockIdx.x * SPAD;

    float m = -1e30f;
    for (int i = tid; i < SP; i += 256) m = fmaxf(m, row[i]);
    #pragma unroll
    for (int o = 16; o; o >>= 1) m = fmaxf(m, __shfl_xor_sync(0xffffffffu, m, o));
    if (lane == 0) red[wid] = m;
    __syncthreads();
    if (tid == 0) {
        float v = red[0];
        for (int i = 1; i < 8; i++) v = fmaxf(v, red[i]);
        bc = v;
    }
    __syncthreads();
    const float M = bc;

    float s = 0.f;
    for (int i = tid; i < SP; i += 256) {
        float e = __expf(row[i] - M);
        row[i] = e;
        s += e;
    }
    #pragma unroll
    for (int o = 16; o; o >>= 1) s += __shfl_xor_sync(0xffffffffu, s, o);
    if (lane == 0) red[wid] = s;
    __syncthreads();
    if (tid == 0) {
        float v = 0.f;
        for (int i = 0; i < 8; i++) v += red[i];
        bc = 1.f / v;
    }
    __syncthreads();
    const float inv = bc;
    for (int i = tid; i < SP; i += 256) row[i] *= inv;
}

// ---------------------------------------------------------------------------
// Kernel 4: value pass — register-direct, all 16 heads per thread (R5 WIN,
// unchanged). grid (VNC, B), 256 threads.
// ---------------------------------------------------------------------------
__global__ void __launch_bounds__(256, 2) k_values(const float* __restrict__ past_value,
                                                   const float* __restrict__ value,
                                                   float* __restrict__ comb_value) {
    __shared__ float as[VCH][20];
    const int chunk = blockIdx.x, b = blockIdx.y, tid = threadIdx.x;
    const int k0 = chunk * VCH;

    for (int i = tid; i < VCH * H; i += 256) {
        int h = i >> 7, k = i & (VCH - 1);
        as[k][h] = (k0 + k < SP) ? g_scores[(size_t)(b * H + h) * SPAD + k0 + k] : 0.f;
    }
    __syncthreads();

    const float* vrow_cur = value + (size_t)b * D + tid * 4;
    const float* pv_base  = past_value + ((size_t)b * S) * D + tid * 4;

    float4 acc[16];
    #pragma unroll
    for (int h = 0; h < 16; h++) acc[h] = make_float4(0.f, 0.f, 0.f, 0.f);

    float4 vbuf[PF];
    #pragma unroll
    for (int p = 0; p < PF; p++) {
        int kp = k0 + p;
        vbuf[p] = *(const float4*)((kp < S) ? pv_base + (size_t)kp * D : vrow_cur);
    }

    for (int kb = 0; kb < VCH; kb += PF) {
        #pragma unroll
        for (int p = 0; p < PF; p++) {
            const int k = kb + p;
            const float4 v = vbuf[p];

            if (kb + PF < VCH) {
                int kn = k0 + k + PF;
                vbuf[p] = *(const float4*)((kn < S) ? pv_base + (size_t)kn * D : vrow_cur);
            }
            int kp = k0 + k;
            if (kp < SP)
                *(float4*)(comb_value + ((size_t)b * SP + kp) * D + tid * 4) = v;

            #pragma unroll
            for (int h4 = 0; h4 < 4; h4++) {
                float4 w = *(const float4*)&as[k][h4 * 4];
                acc[h4 * 4 + 0].x = fmaf(w.x, v.x, acc[h4 * 4 + 0].x);
                acc[h4 * 4 + 0].y = fmaf(w.x, v.y, acc[h4 * 4 + 0].y);
                acc[h4 * 4 + 0].z = fmaf(w.x, v.z, acc[h4 * 4 + 0].z);
                acc[h4 * 4 + 0].w = fmaf(w.x, v.w, acc[h4 * 4 + 0].w);
                acc[h4 * 4 + 1].x = fmaf(w.y, v.x, acc[h4 * 4 + 1].x);
                acc[h4 * 4 + 1].y = fmaf(w.y, v.y, acc[h4 * 4 + 1].y);
                acc[h4 * 4 + 1].z = fmaf(w.y, v.z, acc[h4 * 4 + 1].z);
                acc[h4 * 4 + 1].w = fmaf(w.y, v.w, acc[h4 * 4 + 1].w);
                acc[h4 * 4 + 2].x = fmaf(w.z, v.x, acc[h4 * 4 + 2].x);
                acc[h4 * 4 + 2].y = fmaf(w.z, v.y, acc[h4 * 4 + 2].y);
                acc[h4 * 4 + 2].z = fmaf(w.z, v.z, acc[h4 * 4 + 2].z);
                acc[h4 * 4 + 2].w = fmaf(w.z, v.w, acc[h4 * 4 + 2].w);
                acc[h4 * 4 + 3].x = fmaf(w.w, v.x, acc[h4 * 4 + 3].x);
                acc[h4 * 4 + 3].y = fmaf(w.w, v.y, acc[h4 * 4 + 3].y);
                acc[h4 * 4 + 3].z = fmaf(w.w, v.z, acc[h4 * 4 + 3].z);
                acc[h4 * 4 + 3].w = fmaf(w.w, v.w, acc[h4 * 4 + 3].w);
            }
        }
    }

    #pragma unroll
    for (int h = 0; h < 16; h++)
        *(float4*)&g_avpart[(((size_t)b * VNC + chunk) * H + h) * D + tid * 4] = acc[h];
}

// ---------------------------------------------------------------------------
// Kernel 5: fold chunk partials + ctx = av @ wv^T + bv.  grid (H, B), 256 thr.
// ---------------------------------------------------------------------------
__global__ void __launch_bounds__(256) k_fold(const float* __restrict__ w_in,
                                              const float* __restrict__ b_in) {
    __shared__ float avs[D];
    const int h = blockIdx.x, b = blockIdx.y, tid = threadIdx.x;

    for (int e = tid; e < D; e += 256) {
        float s = 0.f;
        #pragma unroll
        for (int c = 0; c < VNC; c++)
            s += g_avpart[(((size_t)b * VNC + c) * H + h) * D + e];
        avs[e] = s;
    }
    __syncthreads();

    int d = tid >> 2, sub = tid & 3;
    const float* wrow = w_in + (size_t)(2 * D + h * HD + d) * D;
    float a = 0.f;
    #pragma unroll 8
    for (int e = sub; e < D; e += 4) a = fmaf(avs[e], wrow[e], a);
    a += __shfl_down_sync(0xffffffffu, a, 2, 4);
    a += __shfl_down_sync(0xffffffffu, a, 1, 4);
    if (sub == 0) g_ctx[b * D + h * HD + d] = a + b_in[2 * D + h * HD + d];
}

// ---------------------------------------------------------------------------
// Kernel 6: out = ctx @ w_out^T + b_out.  grid (16, B), 256 thr.
// ---------------------------------------------------------------------------
__global__ void __launch_bounds__(256) k_out(const float* __restrict__ w_out,
                                             const float* __restrict__ b_out,
                                             float* __restrict__ out) {
    __shared__ float cs[D];
    const int og = blockIdx.x, b = blockIdx.y, tid = threadIdx.x;

    for (int i = tid; i < D; i += 256) cs[i] = g_ctx[b * D + i];
    __syncthreads();

    int o = og * 64 + (tid >> 2), sub = tid & 3;
    const float* wrow = w_out + (size_t)o * D;
    float a = 0.f;
    #pragma unroll 8
    for (int dt = sub; dt < D; dt += 4) a = fmaf(cs[dt], wrow[dt], a);
    a += __shfl_down_sync(0xffffffffu, a, 2, 4);
    a += __shfl_down_sync(0xffffffffu, a, 1, 4);
    if (sub == 0) out[(size_t)b * D + o] = a + b_out[o];
}

// ---------------------------------------------------------------------------
extern "C" void kernel_launch(void* const* d_in, const int* in_sizes, int n_in,
                              void* d_out, int out_size) {
    (void)in_sizes; (void)n_in; (void)out_size;
    const float* query      = (const float*)d_in[0];
    const float* key        = (const float*)d_in[1];
    const float* value      = (const float*)d_in[2];
    const float* past_key   = (const float*)d_in[3];
    const float* past_value = (const float*)d_in[4];
    const float* w_in       = (const float*)d_in[5];
    const float* b_in       = (const float*)d_in[6];
    const float* w_out      = (const float*)d_in[7];
    const float* b_out      = (const float*)d_in[8];

    float* out        = (float*)d_out;                      // [16,1,1024]
    float* comb_key   = out + (size_t)Bn * D;               // [16,4097,1024]
    float* comb_value = comb_key + (size_t)Bn * SP * D;     // [16,4097,1024]

    cudaFuncSetAttribute(k_keys, cudaFuncAttributeMaxDynamicSharedMemorySize, KSMEM_BYTES);

    k_qproj  <<<dim3(H, Bn),   256>>>(query, w_in, b_in);
    k_keys   <<<dim3(KNC, Bn), 256, KSMEM_BYTES>>>(past_key, key, comb_key);
    k_softmax<<<Bn * H,        256>>>();
    k_values <<<dim3(VNC, Bn), 256>>>(past_value, value, comb_value);
    k_fold   <<<dim3(H, Bn),   256>>>(w_in, b_in);
    k_out    <<<dim3(16, Bn),  256>>>(w_out, b_out, out);
}